// round 1
// baseline (speedup 1.0000x reference)
#include <cuda_runtime.h>
#include <cstdint>

// GRU_20031727468931: 2-layer GRU, T=16384, IN=14, H=100, out = FC(h2[T-1]).
// Persistent 4-CTA cluster pipeline (3 active stages), register-resident weights,
// DSMEM push + mbarrier handshakes, packed fma.rn.f32x2 matvecs.

#define T_STEPS 16384
#define IN_DIM  14
#define H_DIM   100
#define G_DIM   300
#define NT      608   // 19 full warps; 600 compute lanes (2 per gate-row)

#define R_L0 0
#define R_GI 1
#define R_L1 2

struct __align__(16) SmemLayout {
    unsigned long long bar_full[2];    // data-arrival barriers (role-dependent)
    unsigned long long bar_empty[2];   // buffer-free barriers (role-dependent)
    float h_s[104];                    // local hidden state
    float gh_s[304];                   // recurrent matvec results
    float gi_s[304];                   // input-proj results (layer 0 only)
    float inbuf[2][304];               // incoming channel slots (h0 on GI, gi1 on L1)
    float xs[16];                      // staged x[t] (layer 0)
    float red[104];                    // final FC reduction
};

__device__ __forceinline__ uint32_t s2u(const void* p) {
    uint32_t a;
    asm("{.reg .u64 t; cvta.to.shared.u64 t, %1; cvt.u32.u64 %0, t;}" : "=r"(a) : "l"(p));
    return a;
}
__device__ __forceinline__ uint32_t mapa_u32(uint32_t a, uint32_t rank) {
    uint32_t r;
    asm("mapa.shared::cluster.u32 %0, %1, %2;" : "=r"(r) : "r"(a), "r"(rank));
    return r;
}
__device__ __forceinline__ void st_rem_f32(uint32_t a, float v) {
    asm volatile("st.shared::cluster.f32 [%0], %1;" :: "r"(a), "f"(v) : "memory");
}
__device__ __forceinline__ void mbar_init(uint32_t a, uint32_t n) {
    asm volatile("mbarrier.init.shared.b64 [%0], %1;" :: "r"(a), "r"(n) : "memory");
}
__device__ __forceinline__ void arrive_rel_cluster(uint32_t a) {
    asm volatile("mbarrier.arrive.release.cluster.shared::cluster.b64 _, [%0];"
                 :: "r"(a) : "memory");
}
__device__ __forceinline__ void wait_par_acq(uint32_t a, uint32_t parity) {
    asm volatile(
        "{\n\t.reg .pred P;\n"
        "W_%=:\n\t"
        "mbarrier.try_wait.parity.acquire.cluster.shared::cta.b64 P, [%0], %1;\n\t"
        "@!P bra W_%=;\n\t}"
        :: "r"(a), "r"(parity) : "memory");
}
// packed 2-wide fp32 FMA: acc2 += w2 * h2 (lane-wise)
__device__ __forceinline__ void fma2(unsigned long long& acc,
                                     unsigned long long w, unsigned long long h) {
    asm("fma.rn.f32x2 %0, %1, %2, %0;" : "+l"(acc) : "l"(w), "l"(h));
}
__device__ __forceinline__ float unpack_sum(unsigned long long a, unsigned long long b) {
    float l0, h0, l1, h1;
    asm("mov.b64 {%0,%1}, %2;" : "=f"(l0), "=f"(h0) : "l"(a));
    asm("mov.b64 {%0,%1}, %2;" : "=f"(l1), "=f"(h1) : "l"(b));
    return (l0 + l1) + (h0 + h1);
}
__device__ __forceinline__ float sigf(float v) {
    return __fdividef(1.0f, 1.0f + __expf(-v));
}
__device__ __forceinline__ float tanh_fast(float u) {
    float a = fabsf(u);
    float e = __expf(-2.0f * a);
    float m = __fdividef(1.0f - e, 1.0f + e);
    return (u < 0.0f) ? -m : m;
}
__device__ __forceinline__ void cluster_sync_all() {
    asm volatile("barrier.cluster.arrive.aligned;" ::: "memory");
    asm volatile("barrier.cluster.wait.aligned;" ::: "memory");
}

// 25x packed FMA over one 50-element half-row; h half-row must be 8B aligned.
__device__ __forceinline__ float dot50(const unsigned long long* __restrict__ w2,
                                       const unsigned long long* __restrict__ h2) {
    unsigned long long a0 = 0ULL, a1 = 0ULL;
#pragma unroll
    for (int j = 0; j < 24; j += 2) {
        fma2(a0, w2[j],     h2[j]);
        fma2(a1, w2[j + 1], h2[j + 1]);
    }
    fma2(a0, w2[24], h2[24]);
    return unpack_sum(a0, a1);
}

__global__ void __launch_bounds__(NT, 1) __cluster_dims__(4, 1, 1)
gru_cluster_kernel(const float* __restrict__ x,
                   const float* __restrict__ w_ih0, const float* __restrict__ w_hh0,
                   const float* __restrict__ b_ih0, const float* __restrict__ b_hh0,
                   const float* __restrict__ w_ih1, const float* __restrict__ w_hh1,
                   const float* __restrict__ b_ih1, const float* __restrict__ b_hh1,
                   const float* __restrict__ fc_w,  const float* __restrict__ fc_b,
                   float* __restrict__ out)
{
    __shared__ SmemLayout sm;
    uint32_t rank;
    asm("mov.u32 %0, %%cluster_ctarank;" : "=r"(rank));
    const int tid = threadIdx.x;

    const uint32_t a_full  = s2u(&sm.bar_full[0]);
    const uint32_t a_empty = s2u(&sm.bar_empty[0]);
    const uint32_t a_inbuf = s2u(&sm.inbuf[0][0]);

    if (tid == 0) {
        if (rank == R_GI) {
            mbar_init(a_full, 100);     mbar_init(a_full + 8, 100);   // h0 arrivals from L0
            mbar_init(a_empty, 100);    mbar_init(a_empty + 8, 100);  // gi1-slot free from L1
        } else if (rank == R_L1) {
            mbar_init(a_full, 300);     mbar_init(a_full + 8, 300);   // gi1 arrivals from GI
        } else if (rank == R_L0) {
            mbar_init(a_empty, 1);      mbar_init(a_empty + 8, 1);    // h0-slot free from GI
        }
    }
    if (tid < H_DIM) sm.h_s[tid] = 0.0f;
    __syncthreads();
    cluster_sync_all();   // barriers + h init visible cluster-wide before any remote op

    const int  idx  = (tid < 600) ? tid : 599;
    const int  r    = idx >> 1;
    const int  half = idx & 1;
    const bool lead = ((tid & 1) == 0) && (tid < 600);

    if (rank == R_L0) {
        // ---- layer 0: gh0 = h0 @ W_hh0^T ; gi0 = x[t] @ W_ih0^T (on the fly) ----
        unsigned long long wh[25];
        {
            const unsigned long long* gp =
                (const unsigned long long*)(w_hh0 + r * H_DIM + half * 50);
#pragma unroll
            for (int j = 0; j < 25; j++) wh[j] = gp[j];
        }
        float wx[7];
#pragma unroll
        for (int j = 0; j < 7; j++) wx[j] = w_ih0[r * IN_DIM + half * 7 + j];
        const float bh = b_hh0[r];
        const float bi = b_ih0[r];

        float xreg = (tid < IN_DIM) ? x[tid] : 0.0f;

        const uint32_t rem_inbuf = mapa_u32(a_inbuf, R_GI);
        const uint32_t rem_full  = mapa_u32(a_full,  R_GI);

        for (int t = 0; t < T_STEPS; ++t) {
            const int s = t & 1;
            const uint32_t cp = (uint32_t)((t >> 1) & 1);
            const uint32_t pp = cp ^ 1u;

            if (tid < IN_DIM) {
                sm.xs[tid] = xreg;
                if (t + 1 < T_STEPS) xreg = x[(t + 1) * IN_DIM + tid];
            }
            __syncthreads();   // xs + h_s(t-1 gate writes) visible

            const unsigned long long* h2 =
                (const unsigned long long*)(sm.h_s + half * 50);
            float acch = dot50(wh, h2);
            float accx = 0.0f;
#pragma unroll
            for (int j = 0; j < 7; j++) accx = fmaf(wx[j], sm.xs[half * 7 + j], accx);

            float oh = __shfl_down_sync(0xFFFFFFFFu, acch, 1);
            float ox = __shfl_down_sync(0xFFFFFFFFu, accx, 1);
            if (lead) {
                sm.gh_s[r] = acch + oh + bh;
                sm.gi_s[r] = accx + ox + bi;
            }
            __syncthreads();   // gh/gi visible to gate threads

            if (tid < H_DIM) {
                wait_par_acq(a_empty + 8u * (uint32_t)s, pp);  // GI done with slot s (t-2)
                float gr = sm.gi_s[tid]       + sm.gh_s[tid];
                float gz = sm.gi_s[100 + tid] + sm.gh_s[100 + tid];
                float rr = sigf(gr);
                float zz = sigf(gz);
                float u  = sm.gi_s[200 + tid] + rr * sm.gh_s[200 + tid];
                float nn = tanh_fast(u);
                float hn = nn + zz * (sm.h_s[tid] - nn);
                sm.h_s[tid] = hn;
                st_rem_f32(rem_inbuf + (uint32_t)(s * 304 + tid) * 4u, hn);
                arrive_rel_cluster(rem_full + 8u * (uint32_t)s);  // 100 arrivals
            }
        }
    } else if (rank == R_GI) {
        // ---- gi1 = h0[t] @ W_ih1^T ----
        unsigned long long wi[25];
        {
            const unsigned long long* gp =
                (const unsigned long long*)(w_ih1 + r * H_DIM + half * 50);
#pragma unroll
            for (int j = 0; j < 25; j++) wi[j] = gp[j];
        }
        const float bi = b_ih1[r];

        const uint32_t rem_empty_L0 = mapa_u32(a_empty, R_L0);
        const uint32_t rem_inbuf_L1 = mapa_u32(a_inbuf, R_L1);
        const uint32_t rem_full_L1  = mapa_u32(a_full,  R_L1);

        for (int t = 0; t < T_STEPS; ++t) {
            const int s = t & 1;
            const uint32_t cp = (uint32_t)((t >> 1) & 1);
            const uint32_t pp = cp ^ 1u;

            wait_par_acq(a_full + 8u * (uint32_t)s, cp);   // h0[t] arrived

            const unsigned long long* h2 =
                (const unsigned long long*)(sm.inbuf[s] + half * 50);
            float acc = dot50(wi, h2);
            float o = __shfl_down_sync(0xFFFFFFFFu, acc, 1);

            __syncthreads();   // everyone finished reading inbuf[s]
            if (tid == 0) arrive_rel_cluster(rem_empty_L0 + 8u * (uint32_t)s);

            if (lead) {
                float gv = acc + o + bi;
                wait_par_acq(a_empty + 8u * (uint32_t)s, pp);  // L1 freed slot s (t-2)
                st_rem_f32(rem_inbuf_L1 + (uint32_t)(s * 304 + r) * 4u, gv);
                arrive_rel_cluster(rem_full_L1 + 8u * (uint32_t)s);  // 300 arrivals
            }
        }
    } else if (rank == R_L1) {
        // ---- layer 1: gh1 = h1 @ W_hh1^T ; gates with gi1 from GI ----
        unsigned long long wh[25];
        {
            const unsigned long long* gp =
                (const unsigned long long*)(w_hh1 + r * H_DIM + half * 50);
#pragma unroll
            for (int j = 0; j < 25; j++) wh[j] = gp[j];
        }
        const float bh = b_hh1[r];
        const uint32_t rem_empty_GI = mapa_u32(a_empty, R_GI);

        for (int t = 0; t < T_STEPS; ++t) {
            const int s = t & 1;
            const uint32_t cp = (uint32_t)((t >> 1) & 1);

            __syncthreads();   // h_s(t-1 gate writes) visible; gh_s safe to rewrite

            const unsigned long long* h2 =
                (const unsigned long long*)(sm.h_s + half * 50);
            float acch = dot50(wh, h2);
            float oh = __shfl_down_sync(0xFFFFFFFFu, acch, 1);
            if (lead) sm.gh_s[r] = acch + oh + bh;
            __syncthreads();

            if (tid < H_DIM) {
                wait_par_acq(a_full + 8u * (uint32_t)s, cp);   // gi1[t] arrived
                float gr = sm.inbuf[s][tid]       + sm.gh_s[tid];
                float gz = sm.inbuf[s][100 + tid] + sm.gh_s[100 + tid];
                float rr = sigf(gr);
                float zz = sigf(gz);
                float u  = sm.inbuf[s][200 + tid] + rr * sm.gh_s[200 + tid];
                float nn = tanh_fast(u);
                float hn = nn + zz * (sm.h_s[tid] - nn);
                sm.h_s[tid] = hn;
                arrive_rel_cluster(rem_empty_GI + 8u * (uint32_t)s);  // 100 arrivals
            }
        }
        __syncthreads();
        if (tid < H_DIM) sm.red[tid] = sm.h_s[tid] * fc_w[tid];
        __syncthreads();
        if (tid == 0) {
            float sv = fc_b[0];
            for (int j = 0; j < H_DIM; j++) sv += sm.red[j];
            out[0] = sv;
        }
    }
    // rank 3 (idle) and everyone else: final cluster sync so no CTA's smem
    // disappears while peers may still issue remote arrives/stores.
    cluster_sync_all();
}

extern "C" void kernel_launch(void* const* d_in, const int* in_sizes, int n_in,
                              void* d_out, int out_size) {
    const float* x     = (const float*)d_in[0];
    const float* w_ih0 = (const float*)d_in[1];
    const float* w_hh0 = (const float*)d_in[2];
    const float* b_ih0 = (const float*)d_in[3];
    const float* b_hh0 = (const float*)d_in[4];
    const float* w_ih1 = (const float*)d_in[5];
    const float* w_hh1 = (const float*)d_in[6];
    const float* b_ih1 = (const float*)d_in[7];
    const float* b_hh1 = (const float*)d_in[8];
    const float* fc_w  = (const float*)d_in[9];
    const float* fc_b  = (const float*)d_in[10];
    float* out = (float*)d_out;

    gru_cluster_kernel<<<4, NT>>>(x, w_ih0, w_hh0, b_ih0, b_hh0,
                                  w_ih1, w_hh1, b_ih1, b_hh1,
                                  fc_w, fc_b, out);
}

// round 2
// speedup vs baseline: 1.3504x; 1.3504x over previous
#include <cuda_runtime.h>
#include <cstdint>

// GRU_20031727468931: 2-layer GRU, T=16384, IN=14, H=100, out = FC(h2[T-1]).
// 4-CTA cluster pipeline (3 active stages), register-resident weights.
// Round 2: per-thread remote stores/arrives -> one cp.async.bulk DSMEM copy
// (mbarrier complete_tx) + one credit arrive per channel per step.

#define T_STEPS 16384
#define IN_DIM  14
#define H_DIM   100
#define NT      608   // 19 warps; 600 compute lanes (2 per gate-row)

#define R_L0 0
#define R_GI 1
#define R_L1 2

#define H_BYTES  400u   // 100 floats
#define G_BYTES  1200u  // 300 floats

struct __align__(16) SmemLayout {
    unsigned long long bar_full[2];    // data-arrival (tx) barriers, consumer side
    unsigned long long bar_empty[2];   // credit barriers, producer side
    float h_s[100];                    // 400B
    float xs[16];                      // 64B
    float gh_s[300];                   // 1200B
    float gi_s[300];                   // 1200B
    float inbuf[2][300];               // incoming channel slots (16B-aligned each)
    float outbuf[2][300];              // outgoing staging (double buffered)
    float red[100];
};

__device__ __forceinline__ uint32_t s2u(const void* p) {
    uint32_t a;
    asm("{.reg .u64 t; cvta.to.shared.u64 t, %1; cvt.u32.u64 %0, t;}" : "=r"(a) : "l"(p));
    return a;
}
__device__ __forceinline__ uint32_t mapa_u32(uint32_t a, uint32_t rank) {
    uint32_t r;
    asm("mapa.shared::cluster.u32 %0, %1, %2;" : "=r"(r) : "r"(a), "r"(rank));
    return r;
}
__device__ __forceinline__ void mbar_init(uint32_t a, uint32_t n) {
    asm volatile("mbarrier.init.shared.b64 [%0], %1;" :: "r"(a), "r"(n) : "memory");
}
__device__ __forceinline__ void mbar_expect_tx(uint32_t a, uint32_t bytes) {
    asm volatile("mbarrier.arrive.expect_tx.shared.b64 _, [%0], %1;"
                 :: "r"(a), "r"(bytes) : "memory");
}
__device__ __forceinline__ void arrive_rel_cluster(uint32_t a) {
    asm volatile("mbarrier.arrive.release.cluster.shared::cluster.b64 _, [%0];"
                 :: "r"(a) : "memory");
}
__device__ __forceinline__ void wait_par_acq(uint32_t a, uint32_t parity) {
    asm volatile(
        "{\n\t.reg .pred P;\n"
        "W_%=:\n\t"
        "mbarrier.try_wait.parity.acquire.cluster.shared::cta.b64 P, [%0], %1;\n\t"
        "@!P bra W_%=;\n\t}"
        :: "r"(a), "r"(parity) : "memory");
}
__device__ __forceinline__ void fence_proxy_async_cta() {
    asm volatile("fence.proxy.async.shared::cta;" ::: "memory");
}
// one-shot DSMEM bulk copy: local smem -> remote CTA smem, complete_tx at remote mbar
__device__ __forceinline__ void bulk_copy_cluster(uint32_t dst_dsmem, uint32_t src_local,
                                                  uint32_t bytes, uint32_t rem_mbar) {
    asm volatile(
        "cp.async.bulk.shared::cluster.shared::cta.mbarrier::complete_tx::bytes "
        "[%0], [%1], %2, [%3];"
        :: "r"(dst_dsmem), "r"(src_local), "r"(bytes), "r"(rem_mbar) : "memory");
}
__device__ __forceinline__ void bar1_128() {
    asm volatile("bar.sync 1, 128;" ::: "memory");
}
__device__ __forceinline__ void fma2(unsigned long long& acc,
                                     unsigned long long w, unsigned long long h) {
    asm("fma.rn.f32x2 %0, %1, %2, %0;" : "+l"(acc) : "l"(w), "l"(h));
}
__device__ __forceinline__ float unpack_sum(unsigned long long a, unsigned long long b) {
    float l0, h0, l1, h1;
    asm("mov.b64 {%0,%1}, %2;" : "=f"(l0), "=f"(h0) : "l"(a));
    asm("mov.b64 {%0,%1}, %2;" : "=f"(l1), "=f"(h1) : "l"(b));
    return (l0 + l1) + (h0 + h1);
}
__device__ __forceinline__ float sigf(float v) {
    return __fdividef(1.0f, 1.0f + __expf(-v));
}
__device__ __forceinline__ float tanh_fast(float u) {
    float a = fabsf(u);
    float e = __expf(-2.0f * a);
    float m = __fdividef(1.0f - e, 1.0f + e);
    return (u < 0.0f) ? -m : m;
}
__device__ __forceinline__ void cluster_sync_all() {
    asm volatile("barrier.cluster.arrive.aligned;" ::: "memory");
    asm volatile("barrier.cluster.wait.aligned;" ::: "memory");
}

__device__ __forceinline__ float dot50(const unsigned long long* __restrict__ w2,
                                       const unsigned long long* __restrict__ h2) {
    unsigned long long a0 = 0ULL, a1 = 0ULL;
#pragma unroll
    for (int j = 0; j < 24; j += 2) {
        fma2(a0, w2[j],     h2[j]);
        fma2(a1, w2[j + 1], h2[j + 1]);
    }
    fma2(a0, w2[24], h2[24]);
    return unpack_sum(a0, a1);
}

__global__ void __launch_bounds__(NT, 1) __cluster_dims__(4, 1, 1)
gru_cluster_kernel(const float* __restrict__ x,
                   const float* __restrict__ w_ih0, const float* __restrict__ w_hh0,
                   const float* __restrict__ b_ih0, const float* __restrict__ b_hh0,
                   const float* __restrict__ w_ih1, const float* __restrict__ w_hh1,
                   const float* __restrict__ b_ih1, const float* __restrict__ b_hh1,
                   const float* __restrict__ fc_w,  const float* __restrict__ fc_b,
                   float* __restrict__ out)
{
    __shared__ SmemLayout sm;
    uint32_t rank;
    asm("mov.u32 %0, %%cluster_ctarank;" : "=r"(rank));
    const int tid = threadIdx.x;

    const uint32_t a_full  = s2u(&sm.bar_full[0]);
    const uint32_t a_empty = s2u(&sm.bar_empty[0]);
    const uint32_t a_inbuf = s2u(&sm.inbuf[0][0]);

    if (tid == 0) {
        // full barriers: 1 arrival (the expect_tx re-arm) + tx bytes
        mbar_init(a_full,     1);  mbar_init(a_full + 8,  1);
        // empty barriers: 1 credit arrive per phase
        mbar_init(a_empty,    1);  mbar_init(a_empty + 8, 1);
        if (rank == R_GI) {       // arm both slots for h0 (400B)
            mbar_expect_tx(a_full,     H_BYTES);
            mbar_expect_tx(a_full + 8, H_BYTES);
        } else if (rank == R_L1) { // arm both slots for gi1 (1200B)
            mbar_expect_tx(a_full,     G_BYTES);
            mbar_expect_tx(a_full + 8, G_BYTES);
        }
    }
    if (tid < H_DIM) sm.h_s[tid] = 0.0f;
    __syncthreads();
    cluster_sync_all();   // barriers armed + h init visible before any remote op

    const int  idx  = (tid < 600) ? tid : 599;
    const int  r    = idx >> 1;
    const int  half = idx & 1;
    const bool lead = ((tid & 1) == 0) && (tid < 600);

    if (rank == R_L0) {
        // ---- layer 0: gh0 = h0 @ W_hh0^T ; gi0 = x[t] @ W_ih0^T (on the fly) ----
        unsigned long long wh[25];
        {
            const unsigned long long* gp =
                (const unsigned long long*)(w_hh0 + r * H_DIM + half * 50);
#pragma unroll
            for (int j = 0; j < 25; j++) wh[j] = gp[j];
        }
        float wx[7];
#pragma unroll
        for (int j = 0; j < 7; j++) wx[j] = w_ih0[r * IN_DIM + half * 7 + j];
        const float bh = b_hh0[r];
        const float bi = b_ih0[r];

        float xreg = (tid < IN_DIM) ? x[tid] : 0.0f;

        const uint32_t rem_inbuf = mapa_u32(a_inbuf, R_GI);
        const uint32_t rem_full  = mapa_u32(a_full,  R_GI);
        const uint32_t a_out     = s2u(&sm.outbuf[0][0]);

        for (int t = 0; t < T_STEPS; ++t) {
            const int s = t & 1;
            const uint32_t cp = (uint32_t)((t >> 1) & 1);
            const uint32_t pp = cp ^ 1u;

            if (tid < IN_DIM) {
                sm.xs[tid] = xreg;
                if (t + 1 < T_STEPS) xreg = x[(t + 1) * IN_DIM + tid];
            }
            __syncthreads();   // (A) h_s(t-1) + xs visible

            const unsigned long long* h2 =
                (const unsigned long long*)(sm.h_s + half * 50);
            float acch = dot50(wh, h2);
            float accx = 0.0f;
#pragma unroll
            for (int j = 0; j < 7; j++) accx = fmaf(wx[j], sm.xs[half * 7 + j], accx);

            float oh = __shfl_down_sync(0xFFFFFFFFu, acch, 1);
            float ox = __shfl_down_sync(0xFFFFFFFFu, accx, 1);
            if (lead) {
                sm.gh_s[r] = acch + oh + bh;
                sm.gi_s[r] = accx + ox + bi;
            }
            __syncthreads();   // (B) gh/gi visible to gate threads

            if (tid < H_DIM) {
                // credit(t-2) from GI: dest slot free AND copy(t-2) of outbuf[s] done
                wait_par_acq(a_empty + 8u * (uint32_t)s, pp);
                float gr = sm.gi_s[tid]       + sm.gh_s[tid];
                float gz = sm.gi_s[100 + tid] + sm.gh_s[100 + tid];
                float rr = sigf(gr);
                float zz = sigf(gz);
                float u  = sm.gi_s[200 + tid] + rr * sm.gh_s[200 + tid];
                float nn = tanh_fast(u);
                float hn = nn + zz * (sm.h_s[tid] - nn);
                sm.h_s[tid] = hn;
                sm.outbuf[s][tid] = hn;
            }
            if (tid < 128) {
                bar1_128();            // warps 0-3: outbuf[s] complete
                if (tid == 0) {
                    fence_proxy_async_cta();
                    bulk_copy_cluster(rem_inbuf + (uint32_t)s * G_BYTES,
                                      a_out + (uint32_t)s * G_BYTES,
                                      H_BYTES,
                                      rem_full + 8u * (uint32_t)s);
                }
            }
        }
    } else if (rank == R_GI) {
        // ---- gi1 = h0[t] @ W_ih1^T ----
        unsigned long long wi[25];
        {
            const unsigned long long* gp =
                (const unsigned long long*)(w_ih1 + r * H_DIM + half * 50);
#pragma unroll
            for (int j = 0; j < 25; j++) wi[j] = gp[j];
        }
        const float bi = b_ih1[r];

        const uint32_t rem_empty_L0 = mapa_u32(a_empty, R_L0);
        const uint32_t rem_inbuf_L1 = mapa_u32(a_inbuf, R_L1);
        const uint32_t rem_full_L1  = mapa_u32(a_full,  R_L1);
        const uint32_t a_out        = s2u(&sm.outbuf[0][0]);

        for (int t = 0; t < T_STEPS; ++t) {
            const int s = t & 1;
            const uint32_t cp = (uint32_t)((t >> 1) & 1);
            const uint32_t pp = cp ^ 1u;

            wait_par_acq(a_full + 8u * (uint32_t)s, cp);   // h0[t] arrived (tx)
            // L1 credit(t-2): dest slot free AND copy(t-2) of outbuf[s] done
            wait_par_acq(a_empty + 8u * (uint32_t)s, pp);

            const unsigned long long* h2 =
                (const unsigned long long*)(sm.inbuf[s] + half * 50);
            float acc = dot50(wi, h2);
            float o = __shfl_down_sync(0xFFFFFFFFu, acc, 1);
            if (lead) sm.outbuf[s][r] = acc + o + bi;

            __syncthreads();   // inbuf[s] reads done + outbuf[s] ready
            if (tid == 0) {
                mbar_expect_tx(a_full + 8u * (uint32_t)s, H_BYTES);   // re-arm slot s
                arrive_rel_cluster(rem_empty_L0 + 8u * (uint32_t)s);  // credit L0
                fence_proxy_async_cta();
                bulk_copy_cluster(rem_inbuf_L1 + (uint32_t)s * G_BYTES,
                                  a_out + (uint32_t)s * G_BYTES,
                                  G_BYTES,
                                  rem_full_L1 + 8u * (uint32_t)s);
            }
        }
    } else if (rank == R_L1) {
        // ---- layer 1: gh1 = h1 @ W_hh1^T ; gates with gi1 from GI ----
        unsigned long long wh[25];
        {
            const unsigned long long* gp =
                (const unsigned long long*)(w_hh1 + r * H_DIM + half * 50);
#pragma unroll
            for (int j = 0; j < 25; j++) wh[j] = gp[j];
        }
        const float bh = b_hh1[r];
        const uint32_t rem_empty_GI = mapa_u32(a_empty, R_GI);

        for (int t = 0; t < T_STEPS; ++t) {
            const int s = t & 1;
            const uint32_t cp = (uint32_t)((t >> 1) & 1);

            __syncthreads();   // (A) h_s(t-1) gate writes visible; gh_s reusable

            const unsigned long long* h2 =
                (const unsigned long long*)(sm.h_s + half * 50);
            float acch = dot50(wh, h2);
            float oh = __shfl_down_sync(0xFFFFFFFFu, acch, 1);
            if (lead) sm.gh_s[r] = acch + oh + bh;
            __syncthreads();   // (B)

            if (tid < H_DIM) {
                wait_par_acq(a_full + 8u * (uint32_t)s, cp);   // gi1[t] arrived (tx)
                float gr = sm.inbuf[s][tid]       + sm.gh_s[tid];
                float gz = sm.inbuf[s][100 + tid] + sm.gh_s[100 + tid];
                float rr = sigf(gr);
                float zz = sigf(gz);
                float u  = sm.inbuf[s][200 + tid] + rr * sm.gh_s[200 + tid];
                float nn = tanh_fast(u);
                float hn = nn + zz * (sm.h_s[tid] - nn);
                sm.h_s[tid] = hn;
            }
            if (tid < 128) {
                bar1_128();            // all inbuf[s] readers done
                if (tid == 0) {
                    mbar_expect_tx(a_full + 8u * (uint32_t)s, G_BYTES);   // re-arm
                    arrive_rel_cluster(rem_empty_GI + 8u * (uint32_t)s);  // credit GI
                }
            }
        }
        __syncthreads();
        if (tid < H_DIM) sm.red[tid] = sm.h_s[tid] * fc_w[tid];
        __syncthreads();
        if (tid == 0) {
            float sv = fc_b[0];
            for (int j = 0; j < H_DIM; j++) sv += sm.red[j];
            out[0] = sv;
        }
    }
    // final cluster sync: no CTA's smem may vanish while peers still touch it
    cluster_sync_all();
}

extern "C" void kernel_launch(void* const* d_in, const int* in_sizes, int n_in,
                              void* d_out, int out_size) {
    const float* x     = (const float*)d_in[0];
    const float* w_ih0 = (const float*)d_in[1];
    const float* w_hh0 = (const float*)d_in[2];
    const float* b_ih0 = (const float*)d_in[3];
    const float* b_hh0 = (const float*)d_in[4];
    const float* w_ih1 = (const float*)d_in[5];
    const float* w_hh1 = (const float*)d_in[6];
    const float* b_ih1 = (const float*)d_in[7];
    const float* b_hh1 = (const float*)d_in[8];
    const float* fc_w  = (const float*)d_in[9];
    const float* fc_b  = (const float*)d_in[10];
    float* out = (float*)d_out;

    gru_cluster_kernel<<<4, NT>>>(x, w_ih0, w_hh0, b_ih0, b_hh0,
                                  w_ih1, w_hh1, b_ih1, b_hh1,
                                  fc_w, fc_b, out);
}

// round 4
// speedup vs baseline: 2.0112x; 1.4893x over previous
#include <cuda_runtime.h>
#include <cstdint>

// GRU_20031727468931: 2-layer GRU, T=16384, IN=14, H=100, out = FC(h2[T-1]).
// Round 4: identical to Round 3 except the L0 empty-credit parity fix
// (expression had XOR-cancelled to constant 0 -> deadlock).

#define T_STEPS 16384
#define IN_DIM  14
#define H_DIM   100
#define NT      224    // 7 warps; 200 active lanes (pair per gate-row-triple)

#define R_L0 0
#define R_GI 1
#define R_L1 2

#define NSLOT    4
#define SLOT_F   304u                 // floats per slot (16B-aligned stride)
#define SLOT_B   (SLOT_F * 4u)        // 1216 bytes
#define H_BYTES  416u                 // 104 floats (padded h layout)
#define G_BYTES  1200u                // 300 floats

typedef unsigned long long u64;

__device__ float g_gi0[T_STEPS * 300];   // precomputed x @ W_ih0^T + b_ih0

struct __align__(16) SmemLayout {
    u64 bar_full[NSLOT];
    u64 bar_empty[NSLOT];
    float h_s[2][104];        // padded: value i at index i + (i>=50 ? 2 : 0)
    float inbuf[NSLOT][SLOT_F];
    float outbuf[NSLOT][SLOT_F];
    float red[100];
};

__device__ __forceinline__ uint32_t s2u(const void* p) {
    uint32_t a;
    asm("{.reg .u64 t; cvta.to.shared.u64 t, %1; cvt.u32.u64 %0, t;}" : "=r"(a) : "l"(p));
    return a;
}
__device__ __forceinline__ uint32_t mapa_u32(uint32_t a, uint32_t rank) {
    uint32_t r;
    asm("mapa.shared::cluster.u32 %0, %1, %2;" : "=r"(r) : "r"(a), "r"(rank));
    return r;
}
__device__ __forceinline__ void mbar_init(uint32_t a, uint32_t n) {
    asm volatile("mbarrier.init.shared.b64 [%0], %1;" :: "r"(a), "r"(n) : "memory");
}
__device__ __forceinline__ void mbar_arrive_local(uint32_t a) {
    asm volatile("mbarrier.arrive.shared.b64 _, [%0];" :: "r"(a) : "memory");
}
__device__ __forceinline__ void mbar_expect_tx(uint32_t a, uint32_t bytes) {
    asm volatile("mbarrier.arrive.expect_tx.shared.b64 _, [%0], %1;"
                 :: "r"(a), "r"(bytes) : "memory");
}
__device__ __forceinline__ void arrive_rel_cluster(uint32_t a) {
    asm volatile("mbarrier.arrive.release.cluster.shared::cluster.b64 _, [%0];"
                 :: "r"(a) : "memory");
}
__device__ __forceinline__ void wait_par_acq(uint32_t a, uint32_t parity) {
    asm volatile(
        "{\n\t.reg .pred P;\n"
        "W_%=:\n\t"
        "mbarrier.try_wait.parity.acquire.cluster.shared::cta.b64 P, [%0], %1;\n\t"
        "@!P bra W_%=;\n\t}"
        :: "r"(a), "r"(parity) : "memory");
}
__device__ __forceinline__ void fence_pa() {
    asm volatile("fence.proxy.async.shared::cta;" ::: "memory");
}
__device__ __forceinline__ void bulk_copy_cluster(uint32_t dst_dsmem, uint32_t src_local,
                                                  uint32_t bytes, uint32_t rem_mbar) {
    asm volatile(
        "cp.async.bulk.shared::cluster.shared::cta.mbarrier::complete_tx::bytes "
        "[%0], [%1], %2, [%3];"
        :: "r"(dst_dsmem), "r"(src_local), "r"(bytes), "r"(rem_mbar) : "memory");
}
__device__ __forceinline__ void fma2(u64& acc, u64 w, u64 h) {
    asm("fma.rn.f32x2 %0, %1, %2, %0;" : "+l"(acc) : "l"(w), "l"(h));
}
__device__ __forceinline__ float unpack_sum(u64 a, u64 b) {
    float l0, h0, l1, h1;
    asm("mov.b64 {%0,%1}, %2;" : "=f"(l0), "=f"(h0) : "l"(a));
    asm("mov.b64 {%0,%1}, %2;" : "=f"(l1), "=f"(h1) : "l"(b));
    return (l0 + l1) + (h0 + h1);
}
__device__ __forceinline__ float sigf(float v) {
    return __fdividef(1.0f, 1.0f + __expf(-v));
}
__device__ __forceinline__ float tanh_fast(float u) {
    float a = fabsf(u);
    float e = __expf(-2.0f * a);
    float m = __fdividef(1.0f - e, 1.0f + e);
    return (u < 0.0f) ? -m : m;
}
__device__ __forceinline__ void cluster_sync_all() {
    asm volatile("barrier.cluster.arrive.aligned;" ::: "memory");
    asm volatile("barrier.cluster.wait.aligned;" ::: "memory");
}

// 3 simultaneous half-row dots sharing one h half-vector (50 floats).
// hbase: smem float ptr, 16B-aligned, first float of this half (offset half*52).
__device__ __forceinline__ void dot3(const u64* __restrict__ w0,
                                     const u64* __restrict__ w1,
                                     const u64* __restrict__ w2,
                                     const float* __restrict__ hbase,
                                     float& s0, float& s1, float& s2) {
    const ulonglong2* hp = (const ulonglong2*)hbase;
    u64 a0 = 0, b0 = 0, a1 = 0, b1 = 0, a2 = 0, b2 = 0;
#pragma unroll
    for (int j = 0; j < 12; j++) {
        ulonglong2 hv = hp[j];
        fma2(a0, w0[2 * j], hv.x);  fma2(b0, w0[2 * j + 1], hv.y);
        fma2(a1, w1[2 * j], hv.x);  fma2(b1, w1[2 * j + 1], hv.y);
        fma2(a2, w2[2 * j], hv.x);  fma2(b2, w2[2 * j + 1], hv.y);
    }
    u64 htail = ((const u64*)hbase)[24];
    fma2(a0, w0[24], htail);
    fma2(a1, w1[24], htail);
    fma2(a2, w2[24], htail);
    s0 = unpack_sum(a0, b0);
    s1 = unpack_sum(a1, b1);
    s2 = unpack_sum(a2, b2);
}

__device__ __forceinline__ void load_w3(const float* __restrict__ W, int p, int half,
                                        u64* w0, u64* w1, u64* w2) {
    const u64* g0 = (const u64*)(W + (p)       * H_DIM + half * 50);
    const u64* g1 = (const u64*)(W + (p + 100) * H_DIM + half * 50);
    const u64* g2 = (const u64*)(W + (p + 200) * H_DIM + half * 50);
#pragma unroll
    for (int j = 0; j < 25; j++) { w0[j] = g0[j]; w1[j] = g1[j]; w2[j] = g2[j]; }
}

// ---------------- precompute: gi0[t][g] = x[t]·W_ih0[g] + b_ih0[g] ----------------
__global__ void gi0_kernel(const float* __restrict__ x,
                           const float* __restrict__ w_ih0,
                           const float* __restrict__ b_ih0) {
    __shared__ float xs[IN_DIM];
    int t = blockIdx.x;
    int g = threadIdx.x;
    if (g < IN_DIM) xs[g] = x[t * IN_DIM + g];
    __syncthreads();
    if (g < 300) {
        float acc = b_ih0[g];
        const float* wr = w_ih0 + g * IN_DIM;
#pragma unroll
        for (int k = 0; k < IN_DIM; k++) acc = fmaf(wr[k], xs[k], acc);
        g_gi0[t * 300 + g] = acc;
    }
}

// ---------------- main cluster kernel ----------------
__global__ void __launch_bounds__(NT, 1) __cluster_dims__(4, 1, 1)
gru_cluster_kernel(const float* __restrict__ w_hh0, const float* __restrict__ b_hh0,
                   const float* __restrict__ w_ih1, const float* __restrict__ w_hh1,
                   const float* __restrict__ b_ih1, const float* __restrict__ b_hh1,
                   const float* __restrict__ fc_w,  const float* __restrict__ fc_b,
                   float* __restrict__ out)
{
    __shared__ SmemLayout sm;
    uint32_t rank;
    asm("mov.u32 %0, %%cluster_ctarank;" : "=r"(rank));
    const int tid = threadIdx.x;

    const uint32_t a_full  = s2u(&sm.bar_full[0]);
    const uint32_t a_empty = s2u(&sm.bar_empty[0]);
    const uint32_t a_inbuf = s2u(&sm.inbuf[0][0]);
    const uint32_t a_out   = s2u(&sm.outbuf[0][0]);

    if (tid == 0) {
#pragma unroll
        for (int i = 0; i < NSLOT; i++) {
            mbar_init(a_full  + 8u * i, 1);
            mbar_init(a_empty + 8u * i, 1);
            mbar_arrive_local(a_empty + 8u * i);   // pre-grant credit (phase 0)
        }
        if (rank == R_GI) {
#pragma unroll
            for (int i = 0; i < NSLOT; i++) mbar_expect_tx(a_full + 8u * i, H_BYTES);
        } else if (rank == R_L1) {
#pragma unroll
            for (int i = 0; i < NSLOT; i++) mbar_expect_tx(a_full + 8u * i, G_BYTES);
        }
    }
    if (tid < 104) { sm.h_s[0][tid] = 0.0f; sm.h_s[1][tid] = 0.0f; }
    __syncthreads();
    cluster_sync_all();

    const int  idx  = (tid < 200) ? tid : 199;
    const int  p    = idx >> 1;          // pair id = gate row (0..99)
    const int  half = idx & 1;
    const bool lead = ((tid & 1) == 0) && (tid < 200);
    const int  pos  = p + (p >= 50 ? 2 : 0);   // padded h index

    if (rank == R_L0) {
        u64 w0[25], w1[25], w2[25];
        load_w3(w_hh0, p, half, w0, w1, w2);
        const float bh0 = b_hh0[p], bh1 = b_hh0[p + 100], bh2 = b_hh0[p + 200];

        const uint32_t rem_inbuf = mapa_u32(a_inbuf, R_GI);
        const uint32_t rem_full  = mapa_u32(a_full,  R_GI);

        float gc0 = 0.f, gc1 = 0.f, gc2 = 0.f;
        if (lead) {
            gc0 = g_gi0[p]; gc1 = g_gi0[p + 100]; gc2 = g_gi0[p + 200];
        }

        for (int t = 0; t < T_STEPS; ++t) {
            const int s = t & 3;
            const uint32_t par = (uint32_t)((t >> 2) & 1);

            __syncthreads();   // h_s[buf] ready; outbuf[(t-1)&3] writes done
            if (tid == 0 && t > 0) {
                const int sp = (t - 1) & 3;
                fence_pa();
                bulk_copy_cluster(rem_inbuf + (uint32_t)sp * SLOT_B,
                                  a_out + (uint32_t)sp * SLOT_B,
                                  H_BYTES, rem_full + 8u * sp);
            }
            // prefetch next step's gi0 (leads)
            float gn0 = 0.f, gn1 = 0.f, gn2 = 0.f;
            if (lead) {
                int tn = (t + 1 < T_STEPS) ? t + 1 : t;
                gn0 = g_gi0[tn * 300 + p];
                gn1 = g_gi0[tn * 300 + p + 100];
                gn2 = g_gi0[tn * 300 + p + 200];
            }

            const int buf = t & 1;
            float s0, s1, s2;
            dot3(w0, w1, w2, &sm.h_s[buf][half * 52], s0, s1, s2);
            float o0 = __shfl_down_sync(0xFFFFFFFFu, s0, 1);
            float o1 = __shfl_down_sync(0xFFFFFFFFu, s1, 1);
            float o2 = __shfl_down_sync(0xFFFFFFFFu, s2, 1);

            if (lead) {
                wait_par_acq(a_empty + 8u * s, par);   // GI credit: slot s free
                float ghr = s0 + o0 + bh0;
                float ghz = s1 + o1 + bh1;
                float ghn = s2 + o2 + bh2;
                float rr = sigf(gc0 + ghr);
                float zz = sigf(gc1 + ghz);
                float nn = tanh_fast(gc2 + rr * ghn);
                float ho = sm.h_s[buf][pos];
                float hn = nn + zz * (ho - nn);
                sm.h_s[buf ^ 1][pos] = hn;
                sm.outbuf[s][pos] = hn;
            }
            gc0 = gn0; gc1 = gn1; gc2 = gn2;
        }
        __syncthreads();
        if (tid == 0) {   // final copy (slot of t = T-1)
            const int sp = (T_STEPS - 1) & 3;
            fence_pa();
            bulk_copy_cluster(rem_inbuf + (uint32_t)sp * SLOT_B,
                              a_out + (uint32_t)sp * SLOT_B,
                              H_BYTES, rem_full + 8u * sp);
        }
    } else if (rank == R_GI) {
        u64 w0[25], w1[25], w2[25];
        load_w3(w_ih1, p, half, w0, w1, w2);
        const float bi0 = b_ih1[p], bi1 = b_ih1[p + 100], bi2 = b_ih1[p + 200];

        const uint32_t rem_empty_L0 = mapa_u32(a_empty, R_L0);
        const uint32_t rem_inbuf_L1 = mapa_u32(a_inbuf, R_L1);
        const uint32_t rem_full_L1  = mapa_u32(a_full,  R_L1);

        for (int t = 0; t < T_STEPS; ++t) {
            const int s = t & 3;
            const uint32_t par = (uint32_t)((t >> 2) & 1);

            __syncthreads();   // inbuf[(t-1)&3] reads + outbuf[(t-1)&3] writes done
            if (tid == 0 && t > 0) {
                const int sp = (t - 1) & 3;
                mbar_expect_tx(a_full + 8u * sp, H_BYTES);          // re-arm
                arrive_rel_cluster(rem_empty_L0 + 8u * sp);         // credit L0
                fence_pa();
                bulk_copy_cluster(rem_inbuf_L1 + (uint32_t)sp * SLOT_B,
                                  a_out + (uint32_t)sp * SLOT_B,
                                  G_BYTES, rem_full_L1 + 8u * sp);
            }
            wait_par_acq(a_full + 8u * s, par);      // h0[t] arrived

            float s0, s1, s2;
            dot3(w0, w1, w2, &sm.inbuf[s][half * 52], s0, s1, s2);
            float o0 = __shfl_down_sync(0xFFFFFFFFu, s0, 1);
            float o1 = __shfl_down_sync(0xFFFFFFFFu, s1, 1);
            float o2 = __shfl_down_sync(0xFFFFFFFFu, s2, 1);

            if (lead) {
                wait_par_acq(a_empty + 8u * s, par);  // L1 freed outbuf slot
                sm.outbuf[s][p]       = s0 + o0 + bi0;
                sm.outbuf[s][p + 100] = s1 + o1 + bi1;
                sm.outbuf[s][p + 200] = s2 + o2 + bi2;
            }
        }
        __syncthreads();
        if (tid == 0) {
            const int sp = (T_STEPS - 1) & 3;
            fence_pa();
            bulk_copy_cluster(rem_inbuf_L1 + (uint32_t)sp * SLOT_B,
                              a_out + (uint32_t)sp * SLOT_B,
                              G_BYTES, rem_full_L1 + 8u * sp);
        }
    } else if (rank == R_L1) {
        u64 w0[25], w1[25], w2[25];
        load_w3(w_hh1, p, half, w0, w1, w2);
        const float bh0 = b_hh1[p], bh1 = b_hh1[p + 100], bh2 = b_hh1[p + 200];
        const uint32_t rem_empty_GI = mapa_u32(a_empty, R_GI);

        for (int t = 0; t < T_STEPS; ++t) {
            const int s = t & 3;
            const uint32_t par = (uint32_t)((t >> 2) & 1);

            __syncthreads();   // h_s writes + inbuf[(t-1)&3] reads done
            if (tid == 0 && t > 0) {
                const int sp = (t - 1) & 3;
                mbar_expect_tx(a_full + 8u * sp, G_BYTES);          // re-arm
                arrive_rel_cluster(rem_empty_GI + 8u * sp);         // credit GI
            }

            const int buf = t & 1;
            float s0, s1, s2;
            dot3(w0, w1, w2, &sm.h_s[buf][half * 52], s0, s1, s2);
            float o0 = __shfl_down_sync(0xFFFFFFFFu, s0, 1);
            float o1 = __shfl_down_sync(0xFFFFFFFFu, s1, 1);
            float o2 = __shfl_down_sync(0xFFFFFFFFu, s2, 1);

            if (lead) {
                wait_par_acq(a_full + 8u * s, par);   // gi1[t] arrived
                float ghr = s0 + o0 + bh0;
                float ghz = s1 + o1 + bh1;
                float ghn = s2 + o2 + bh2;
                float rr = sigf(sm.inbuf[s][p]       + ghr);
                float zz = sigf(sm.inbuf[s][p + 100] + ghz);
                float nn = tanh_fast(sm.inbuf[s][p + 200] + rr * ghn);
                float ho = sm.h_s[buf][pos];
                float hn = nn + zz * (ho - nn);
                sm.h_s[buf ^ 1][pos] = hn;
            }
        }
        __syncthreads();
        if (tid < 100) sm.red[tid] = sm.h_s[0][tid + (tid >= 50 ? 2 : 0)] * fc_w[tid];
        __syncthreads();
        if (tid == 0) {
            float sv = fc_b[0];
            for (int j = 0; j < 100; j++) sv += sm.red[j];
            out[0] = sv;
        }
    }
    cluster_sync_all();
}

extern "C" void kernel_launch(void* const* d_in, const int* in_sizes, int n_in,
                              void* d_out, int out_size) {
    const float* x     = (const float*)d_in[0];
    const float* w_ih0 = (const float*)d_in[1];
    const float* w_hh0 = (const float*)d_in[2];
    const float* b_ih0 = (const float*)d_in[3];
    const float* b_hh0 = (const float*)d_in[4];
    const float* w_ih1 = (const float*)d_in[5];
    const float* w_hh1 = (const float*)d_in[6];
    const float* b_ih1 = (const float*)d_in[7];
    const float* b_hh1 = (const float*)d_in[8];
    const float* fc_w  = (const float*)d_in[9];
    const float* fc_b  = (const float*)d_in[10];
    float* out = (float*)d_out;

    gi0_kernel<<<T_STEPS, 320>>>(x, w_ih0, b_ih0);
    gru_cluster_kernel<<<4, NT>>>(w_hh0, b_hh0, w_ih1, w_hh1,
                                  b_ih1, b_hh1, fc_w, fc_b, out);
}